// round 9
// baseline (speedup 1.0000x reference)
#include <cuda_runtime.h>
#include <cuda_bf16.h>
#include <math.h>

#define HDIM 1024
#define NH   32      // N/2
#define LSEQ 4096
#define TPB  128
#define TL   32      // l-values per thread (TPB*TL == LSEQ)

// Accurate fp32 sincos for x in [0, ~1e5). Cody-Waite 3-constant pi/2 reduction
// + cephes minimax polynomials. All explicit __fmaf_rn so fast-math can't degrade it.
__device__ __forceinline__ void sincos_acc(float x, float* sp_out, float* cp_out) {
    // quadrant
    int q = __float2int_rn(__fmul_rn(x, 0.636619772367581343f)); // 2/pi
    float fj = (float)q;
    // r = x - q*(pi/2), pi/2 = C1 + C2 + C3 (C1 exact at 7 mantissa bits)
    float r = __fmaf_rn(fj, -1.5703125f, x);
    r = __fmaf_rn(fj, -4.837512969970703125e-4f, r);
    r = __fmaf_rn(fj, -7.54978995489188236e-8f, r);
    float r2 = __fmul_rn(r, r);
    // sin(r), |r| <= pi/4
    float sp = __fmaf_rn(r2, -1.9515295891e-4f, 8.3321608736e-3f);
    sp = __fmaf_rn(r2, sp, -1.6666654611e-1f);
    float sr = __fmaf_rn(__fmul_rn(r, r2), sp, r);
    // cos(r)
    float cp = __fmaf_rn(r2, 2.443315711809948e-5f, -1.388731625493765e-3f);
    cp = __fmaf_rn(r2, cp, 4.166664568298827e-2f);
    float cr = __fmaf_rn(__fmul_rn(r2, r2), cp, __fmaf_rn(r2, -0.5f, 1.0f));
    int qq = q & 3;
    float s = (qq & 1) ? cr : sr;
    float c = (qq & 1) ? sr : cr;
    if (qq & 2) s = -s;
    if ((qq + 1) & 2) c = -c;
    *sp_out = s;
    *cp_out = c;
}

__global__ __launch_bounds__(TPB, 8)
void s4d_kernel(const float* __restrict__ C,
                const float* __restrict__ log_dt,
                const float* __restrict__ log_A_real,
                const float* __restrict__ A_imag,
                float* __restrict__ out) {
    __shared__ float s_ar[NH], s_ai[NH], s_wr[NH], s_wi[NH], s_cr[NH], s_ci[NH];

    const int h   = blockIdx.x;
    const int tid = threadIdx.x;

    // ---- per-h parameter precompute (threads 0..31, n = tid) ----
    if (tid < NH) {
        const int n = tid;
        // dt must match fp32-rounded exp as closely as possible: correctly
        // rounded via double. Phase is amplified by l up to 4096 -> ulp matters.
        float dt = (float)exp((double)log_dt[h]);
        float Ar = -expf(log_A_real[h * NH + n]);
        float Ai = A_imag[h * NH + n];
        float ar = __fmul_rn(Ar, dt);   // Re(dtA), matches ref complex*real rounding
        float ai = __fmul_rn(Ai, dt);   // Im(dtA)
        // w = exp(dtA)
        float sw, cw;
        sincos_acc(ai, &sw, &cw);
        float ew = expf(ar);
        float wr = __fmul_rn(ew, cw);
        float wi = __fmul_rn(ew, sw);
        // Cm = Cc * (w - 1) / A
        float nr = wr - 1.0f, ni = wi;
        float den = Ar * Ar + Ai * Ai;
        float inv = 1.0f / den;
        float qr = (nr * Ar + ni * Ai) * inv;
        float qi = (ni * Ar - nr * Ai) * inv;
        float Ccr = C[(h * NH + n) * 2 + 0];
        float Cci = C[(h * NH + n) * 2 + 1];
        s_cr[n] = Ccr * qr - Cci * qi;
        s_ci[n] = Ccr * qi + Cci * qr;
        s_ar[n] = ar;
        s_ai[n] = ai;
        s_wr[n] = wr;
        s_wi[n] = wi;
    }
    __syncthreads();

    float acc[TL];
#pragma unroll
    for (int t = 0; t < TL; t++) acc[t] = 0.0f;

    const int   l0  = tid * TL;
    const float lf0 = (float)l0;

    for (int n = 0; n < NH; n++) {
        const float ai = s_ai[n], ar = s_ar[n];
        const float wr = s_wr[n], wi = s_wi[n];
        const float cr = s_cr[n], ci = s_ci[n];

        // exact anchor at l0, at the reference's rounded angle p0 = fl(ai*lf0)
        float p0   = __fmul_rn(ai, lf0);
        float res0 = __fmaf_rn(ai, lf0, -p0);   // exact - rounded
        float sz, cz;
        sincos_acc(p0, &sz, &cz);
        float ex = expf(__fmul_rn(ar, lf0));
        float zr = ex * cz, zi = ex * sz;
        // fold Cm in: y = Cm * z
        float yr = cr * zr - ci * zi;
        float yi = cr * zi + ci * zr;

#pragma unroll
        for (int t = 0; t < TL; t++) {
            const float lf = lf0 + (float)t;
            // phase-match to the reference's per-element rounded angle:
            // chain angle = p0 + t*ai (exact); ref angle = fl(ai*lf).
            // rotate by phi = res0 - res_l (first order).
            float p   = __fmul_rn(ai, lf);
            float res = __fmaf_rn(ai, lf, -p);
            float phi = res0 - res;
            acc[t] += __fmaf_rn(-phi, yi, yr);
            // y *= w
            float t1  = __fmul_rn(yi, wi);
            float t2  = __fmul_rn(yi, wr);
            float nyr = __fmaf_rn(yr, wr, -t1);
            float nyi = __fmaf_rn(yr, wi, t2);
            yr = nyr;
            yi = nyi;
        }
    }

    float* o = out + (size_t)h * LSEQ + l0;
#pragma unroll
    for (int t = 0; t < TL; t++) o[t] = 2.0f * acc[t];
}

extern "C" void kernel_launch(void* const* d_in, const int* in_sizes, int n_in,
                              void* d_out, int out_size) {
    const float* C          = (const float*)d_in[0];
    const float* log_dt     = (const float*)d_in[1];
    const float* log_A_real = (const float*)d_in[2];
    const float* A_imag     = (const float*)d_in[3];
    float* out = (float*)d_out;
    (void)in_sizes; (void)n_in; (void)out_size;
    s4d_kernel<<<HDIM, TPB>>>(C, log_dt, log_A_real, A_imag, out);
}

// round 15
// speedup vs baseline: 1.6584x; 1.6584x over previous
#include <cuda_runtime.h>
#include <cuda_bf16.h>
#include <math.h>

#define HDIM 1024
#define NH   32      // N/2
#define LSEQ 4096
#define TPB  128
#define TL   32      // l-values per thread (TPB*TL == LSEQ)

// Accurate fp32 sincos for x in [0, ~1e5). Cody-Waite 3-constant pi/2 reduction
// + cephes minimax polynomials. All explicit __fmaf_rn so fast-math can't degrade it.
__device__ __forceinline__ void sincos_acc(float x, float* sp_out, float* cp_out) {
    int q = __float2int_rn(__fmul_rn(x, 0.636619772367581343f)); // 2/pi
    float fj = (float)q;
    float r = __fmaf_rn(fj, -1.5703125f, x);
    r = __fmaf_rn(fj, -4.837512969970703125e-4f, r);
    r = __fmaf_rn(fj, -7.54978995489188236e-8f, r);
    float r2 = __fmul_rn(r, r);
    float sp = __fmaf_rn(r2, -1.9515295891e-4f, 8.3321608736e-3f);
    sp = __fmaf_rn(r2, sp, -1.6666654611e-1f);
    float sr = __fmaf_rn(__fmul_rn(r, r2), sp, r);
    float cp = __fmaf_rn(r2, 2.443315711809948e-5f, -1.388731625493765e-3f);
    cp = __fmaf_rn(r2, cp, 4.166664568298827e-2f);
    float cr = __fmaf_rn(__fmul_rn(r2, r2), cp, __fmaf_rn(r2, -0.5f, 1.0f));
    int qq = q & 3;
    float s = (qq & 1) ? cr : sr;
    float c = (qq & 1) ? sr : cr;
    if (qq & 2) s = -s;
    if ((qq + 1) & 2) c = -c;
    *sp_out = s;
    *cp_out = c;
}

__global__ __launch_bounds__(TPB, 8)
void s4d_kernel(const float* __restrict__ C,
                const float* __restrict__ log_dt,
                const float* __restrict__ log_A_real,
                const float* __restrict__ A_imag,
                float* __restrict__ out) {
    __shared__ float s_ar[NH], s_ai[NH], s_wr[NH], s_wi[NH], s_cr[NH], s_ci[NH];

    const int h   = blockIdx.x;
    const int tid = threadIdx.x;

    // ---- per-h parameter precompute (threads 0..31, n = tid) ----
    if (tid < NH) {
        const int n = tid;
        // dt must match fp32-rounded exp as closely as possible: correctly
        // rounded via double. Phase is amplified by l up to 4096 -> ulp matters.
        float dt = (float)exp((double)log_dt[h]);
        float Ar = -expf(log_A_real[h * NH + n]);
        float Ai = A_imag[h * NH + n];
        float ar = __fmul_rn(Ar, dt);   // Re(dtA), matches ref complex*real rounding
        float ai = __fmul_rn(Ai, dt);   // Im(dtA)
        // w = exp(dtA)
        float sw, cw;
        sincos_acc(ai, &sw, &cw);
        float ew = expf(ar);
        float wr = __fmul_rn(ew, cw);
        float wi = __fmul_rn(ew, sw);
        // Cm = Cc * (w - 1) / A
        float nr = wr - 1.0f, ni = wi;
        float den = Ar * Ar + Ai * Ai;
        float inv = 1.0f / den;
        float qr = (nr * Ar + ni * Ai) * inv;
        float qi = (ni * Ar - nr * Ai) * inv;
        float Ccr = C[(h * NH + n) * 2 + 0];
        float Cci = C[(h * NH + n) * 2 + 1];
        s_cr[n] = Ccr * qr - Cci * qi;
        s_ci[n] = Ccr * qi + Cci * qr;
        s_ar[n] = ar;
        s_ai[n] = ai;
        s_wr[n] = wr;
        s_wi[n] = wi;
    }
    __syncthreads();

    float acc[TL];
#pragma unroll
    for (int t = 0; t < TL; t++) acc[t] = 0.0f;

    const int   l0  = tid * TL;
    const float lf0 = (float)l0;

    for (int n = 0; n < NH; n++) {
        const float ai = s_ai[n], ar = s_ar[n];
        const float wr = s_wr[n], wi = s_wi[n];
        const float cr = s_cr[n], ci = s_ci[n];

        // Anchor at l0. Reference's angle is fl(ai*lf0); we carry the EXACT
        // angle ai*lf0 by rotating the anchor through the rounding residual
        // res0 = ai*lf0 - fl(ai*lf0) (first-order rotation, |res0| <= ~2e-4).
        // Live terms (exp(ar*l) non-negligible) then differ from the reference
        // only by the reference's own per-element rounding (<= 0.5 ulp of a
        // <= ~4e3 rad angle => <= ~1.2e-4 rad), well inside the 1e-3 budget.
        float p0   = __fmul_rn(ai, lf0);
        float res0 = __fmaf_rn(ai, lf0, -p0);   // exact - rounded
        float sz, cz;
        sincos_acc(p0, &sz, &cz);
        float ex = expf(__fmul_rn(ar, lf0));
        float zr0 = ex * cz, zi0 = ex * sz;
        // rotate anchor by res0: z *= (1 + i*res0) (first order)
        float zr = __fmaf_rn(-res0, zi0, zr0);
        float zi = __fmaf_rn( res0, zr0, zi0);
        // fold Cm in: y = Cm * z
        float yr = cr * zr - ci * zi;
        float yi = cr * zi + ci * zr;

#pragma unroll
        for (int t = 0; t < TL; t++) {
            acc[t] += yr;
            // y *= w
            float t1  = __fmul_rn(yi, wi);
            float t2  = __fmul_rn(yi, wr);
            float nyr = __fmaf_rn(yr, wr, -t1);
            float nyi = __fmaf_rn(yr, wi, t2);
            yr = nyr;
            yi = nyi;
        }
    }

    float* o = out + (size_t)h * LSEQ + l0;
#pragma unroll
    for (int t = 0; t < TL; t++) o[t] = 2.0f * acc[t];
}

extern "C" void kernel_launch(void* const* d_in, const int* in_sizes, int n_in,
                              void* d_out, int out_size) {
    const float* C          = (const float*)d_in[0];
    const float* log_dt     = (const float*)d_in[1];
    const float* log_A_real = (const float*)d_in[2];
    const float* A_imag     = (const float*)d_in[3];
    float* out = (float*)d_out;
    (void)in_sizes; (void)n_in; (void)out_size;
    s4d_kernel<<<HDIM, TPB>>>(C, log_dt, log_A_real, A_imag, out);
}